// round 7
// baseline (speedup 1.0000x reference)
#include <cuda_runtime.h>
#include <cuda_bf16.h>
#include <math.h>
#include <stdint.h>

// ---------------- problem constants ----------------
#define BS      2
#define NQ      40000
#define NV      40000
#define EMBED   256
#define HEADS   8
#define POINTS  4
#define HEAD_DIM 32
#define SH      200
#define SW      200
#define MROWS   (BS * NQ)      // 80000

// ---------------- device scratch ----------------
__device__ __nv_bfloat16 g_v[(size_t)BS * NV * EMBED];   // projected value (bf16)
__device__ float g_oa  [(size_t)BS * NQ * 96];           // fused [off(64) | attn(32)]
__device__ float g_tmp [(size_t)BS * NQ * EMBED];
__device__ float g_boa [96];
// transposed + split weights: [N][K] bf16
__device__ __nv_bfloat16 g_Wv_hi [256 * 256], g_Wv_lo [256 * 256];
__device__ __nv_bfloat16 g_Wo_hi [256 * 256], g_Wo_lo [256 * 256];
__device__ __nv_bfloat16 g_Woa_hi[ 96 * 256], g_Woa_lo[ 96 * 256];

// ---------------- warp mma / ldmatrix helpers ----------------
__device__ __forceinline__ void mma_bf16(float* d, const uint32_t* a, const uint32_t* b) {
    asm volatile(
        "mma.sync.aligned.m16n8k16.row.col.f32.bf16.bf16.f32 "
        "{%0,%1,%2,%3}, {%4,%5,%6,%7}, {%8,%9}, {%0,%1,%2,%3};"
        : "+f"(d[0]), "+f"(d[1]), "+f"(d[2]), "+f"(d[3])
        : "r"(a[0]), "r"(a[1]), "r"(a[2]), "r"(a[3]), "r"(b[0]), "r"(b[1]));
}
__device__ __forceinline__ void ldsm_x4(uint32_t& r0, uint32_t& r1, uint32_t& r2, uint32_t& r3,
                                        uint32_t addr) {
    asm volatile("ldmatrix.sync.aligned.m8n8.x4.shared.b16 {%0,%1,%2,%3}, [%4];"
                 : "=r"(r0), "=r"(r1), "=r"(r2), "=r"(r3) : "r"(addr));
}
__device__ __forceinline__ void ldsm_x2(uint32_t& r0, uint32_t& r1, uint32_t addr) {
    asm volatile("ldmatrix.sync.aligned.m8n8.x2.shared.b16 {%0,%1}, [%2];"
                 : "=r"(r0), "=r"(r1) : "r"(addr));
}

// ---------------- weight transpose + bf16 split ----------------
__global__ void convert_w_kernel(const float* __restrict__ W,
                                 __nv_bfloat16* __restrict__ hi,
                                 __nv_bfloat16* __restrict__ lo, int N)
{
    int idx = blockIdx.x * 256 + threadIdx.x;
    if (idx >= N * 256) return;
    int n = idx >> 8, k = idx & 255;
    float v = W[k * N + n];
    __nv_bfloat16 h = __float2bfloat16(v);
    hi[idx] = h;
    lo[idx] = __float2bfloat16(v - __bfloat162float(h));
}

__global__ void convert_oa_kernel(const float* __restrict__ Woff, const float* __restrict__ boff,
                                  const float* __restrict__ Wattn, const float* __restrict__ battn,
                                  __nv_bfloat16* __restrict__ hi, __nv_bfloat16* __restrict__ lo,
                                  float* __restrict__ bcomb)
{
    int idx = blockIdx.x * 256 + threadIdx.x;
    if (idx >= 96 * 256) return;
    int n = idx >> 8, k = idx & 255;
    float v = (n < 64) ? Woff[k * 64 + n] : Wattn[k * 32 + (n - 64)];
    __nv_bfloat16 h = __float2bfloat16(v);
    hi[idx] = h;
    lo[idx] = __float2bfloat16(v - __bfloat162float(h));
    if (idx < 96) bcomb[idx] = (idx < 64) ? boff[idx] : battn[idx - 64];
}

// ---------------- split-bf16 HMMA GEMM: ldmatrix fragment loads ----------------
// CTA tile: 128 x BN. gridDim.y splits total N. 8 warps, warp tile 64 x (BN/4).
// OutT = float (optionally + residual) or __nv_bfloat16.
template<int BN, bool RES, typename OutT>
__global__ void __launch_bounds__(256, 2)
mma_gemm_kernel(const float* __restrict__ A,
                const __nv_bfloat16* __restrict__ Bt_hi,
                const __nv_bfloat16* __restrict__ Bt_lo,
                const float* __restrict__ bias,
                const float* __restrict__ res,
                OutT* __restrict__ C, int ldC)
{
    constexpr int K = 256, BK = 64, BM = 128;
    constexpr int WN  = 4;
    constexpr int WTN = BN / WN;           // 32 or 24 cols per warp
    constexpr int MT  = 4;                 // 64 rows per warp / 16
    constexpr int NTI = WTN / 8;           // 4 or 3
    constexpr int NPAIR = NTI / 2;
    constexpr int AST = 144;
    constexpr int A_H = 0;
    constexpr int A_L = BM * AST;
    constexpr int B_H = 2 * BM * AST;
    constexpr int B_L = B_H + BN * AST;

    extern __shared__ char sm[];

    const int tid  = threadIdx.x;
    const int wid  = tid >> 5;
    const int lane = tid & 31;
    const int g    = lane >> 2;
    const int c    = lane & 3;
    const int wm   = wid / WN;
    const int wn   = wid % WN;
    const int wmBase = wm * 64;
    const int wnBase = wn * WTN;
    const int bm   = blockIdx.x;
    const int nOff = blockIdx.y * BN;

    float acc[MT][NTI][4];
#pragma unroll
    for (int i = 0; i < MT; i++)
#pragma unroll
        for (int j = 0; j < NTI; j++)
#pragma unroll
            for (int q = 0; q < 4; q++) acc[i][j][q] = 0.f;

    const int aRow = wmBase + (lane & 15);
    const int aKs  = (lane >> 4) * 16;
    const int bRow = wnBase + ((lane >> 4) << 3) + (lane & 7);
    const int bKs  = ((lane >> 3) & 1) * 16;
    const uint32_t aHiB = (uint32_t)__cvta_generic_to_shared(sm + A_H + aRow * AST + aKs);
    const uint32_t aLoB = aHiB + (uint32_t)(A_L - A_H);
    const uint32_t bHiB = (uint32_t)__cvta_generic_to_shared(sm + B_H + bRow * AST + bKs);
    const uint32_t bLoB = bHiB + (uint32_t)(B_L - B_H);

    for (int it = 0; it < K / BK; it++) {
        const int k0 = it * BK;
#pragma unroll
        for (int f = tid; f < BM * 16; f += 256) {
            const int r = f >> 4, c4 = f & 15;
            float4 a = *reinterpret_cast<const float4*>(
                &A[(size_t)(bm * BM + r) * K + k0 + c4 * 4]);
            __nv_bfloat16 h0 = __float2bfloat16(a.x);
            __nv_bfloat16 h1 = __float2bfloat16(a.y);
            __nv_bfloat16 h2 = __float2bfloat16(a.z);
            __nv_bfloat16 h3 = __float2bfloat16(a.w);
            __nv_bfloat16 l0 = __float2bfloat16(a.x - __bfloat162float(h0));
            __nv_bfloat16 l1 = __float2bfloat16(a.y - __bfloat162float(h1));
            __nv_bfloat16 l2 = __float2bfloat16(a.z - __bfloat162float(h2));
            __nv_bfloat16 l3 = __float2bfloat16(a.w - __bfloat162float(h3));
            uint32_t hA = ((uint32_t)__bfloat16_as_ushort(h1) << 16) | __bfloat16_as_ushort(h0);
            uint32_t hB = ((uint32_t)__bfloat16_as_ushort(h3) << 16) | __bfloat16_as_ushort(h2);
            uint32_t lA = ((uint32_t)__bfloat16_as_ushort(l1) << 16) | __bfloat16_as_ushort(l0);
            uint32_t lB = ((uint32_t)__bfloat16_as_ushort(l3) << 16) | __bfloat16_as_ushort(l2);
            uint2 vh; vh.x = hA; vh.y = hB;
            uint2 vl; vl.x = lA; vl.y = lB;
            *reinterpret_cast<uint2*>(sm + A_H + r * AST + c4 * 8) = vh;
            *reinterpret_cast<uint2*>(sm + A_L + r * AST + c4 * 8) = vl;
        }
#pragma unroll
        for (int f = tid; f < BN * 8; f += 256) {
            const int n = f >> 3, cu = f & 7;
            uint4 hi = *reinterpret_cast<const uint4*>(&Bt_hi[(nOff + n) * K + k0 + cu * 8]);
            uint4 lo = *reinterpret_cast<const uint4*>(&Bt_lo[(nOff + n) * K + k0 + cu * 8]);
            *reinterpret_cast<uint4*>(sm + B_H + n * AST + cu * 16) = hi;
            *reinterpret_cast<uint4*>(sm + B_L + n * AST + cu * 16) = lo;
        }
        __syncthreads();

#pragma unroll
        for (int ks = 0; ks < BK / 16; ks++) {
            const uint32_t kb = ks * 32;
            uint32_t af[MT][4], bh[NTI][2], bl[NTI][2];
#pragma unroll
            for (int p = 0; p < NPAIR; p++)
                ldsm_x4(bh[2*p][0], bh[2*p][1], bh[2*p+1][0], bh[2*p+1][1],
                        bHiB + (uint32_t)(p * 16 * AST) + kb);
            if (NTI & 1)
                ldsm_x2(bh[NTI-1][0], bh[NTI-1][1],
                        bHiB + (uint32_t)((NTI-1) * 8 * AST) + kb);
#pragma unroll
            for (int mi = 0; mi < MT; mi++)
                ldsm_x4(af[mi][0], af[mi][1], af[mi][2], af[mi][3],
                        aHiB + (uint32_t)(mi * 16 * AST) + kb);
#pragma unroll
            for (int mi = 0; mi < MT; mi++)
#pragma unroll
                for (int ni = 0; ni < NTI; ni++)
                    mma_bf16(acc[mi][ni], af[mi], bh[ni]);
#pragma unroll
            for (int p = 0; p < NPAIR; p++)
                ldsm_x4(bl[2*p][0], bl[2*p][1], bl[2*p+1][0], bl[2*p+1][1],
                        bLoB + (uint32_t)(p * 16 * AST) + kb);
            if (NTI & 1)
                ldsm_x2(bl[NTI-1][0], bl[NTI-1][1],
                        bLoB + (uint32_t)((NTI-1) * 8 * AST) + kb);
#pragma unroll
            for (int mi = 0; mi < MT; mi++)
#pragma unroll
                for (int ni = 0; ni < NTI; ni++)
                    mma_bf16(acc[mi][ni], af[mi], bl[ni]);
#pragma unroll
            for (int mi = 0; mi < MT; mi++)
                ldsm_x4(af[mi][0], af[mi][1], af[mi][2], af[mi][3],
                        aLoB + (uint32_t)(mi * 16 * AST) + kb);
#pragma unroll
            for (int mi = 0; mi < MT; mi++)
#pragma unroll
                for (int ni = 0; ni < NTI; ni++)
                    mma_bf16(acc[mi][ni], af[mi], bh[ni]);
        }
        __syncthreads();
    }

    // ---- epilogue ----
#pragma unroll
    for (int mi = 0; mi < MT; mi++) {
        const int row0 = bm * BM + wmBase + mi * 16 + g;
#pragma unroll
        for (int ni = 0; ni < NTI; ni++) {
            const int col = nOff + wnBase + ni * 8 + c * 2;
            float2 bb = *reinterpret_cast<const float2*>(&bias[col]);
            float2 o0, o1;
            o0.x = acc[mi][ni][0] + bb.x;
            o0.y = acc[mi][ni][1] + bb.y;
            o1.x = acc[mi][ni][2] + bb.x;
            o1.y = acc[mi][ni][3] + bb.y;
            if constexpr (RES) {
                const float* rf = (const float*)res;
                float2 r0 = *reinterpret_cast<const float2*>(&rf[(size_t)row0 * ldC + col]);
                float2 r1 = *reinterpret_cast<const float2*>(&rf[(size_t)(row0 + 8) * ldC + col]);
                o0.x += r0.x; o0.y += r0.y;
                o1.x += r1.x; o1.y += r1.y;
            }
            if constexpr (sizeof(OutT) == 2) {
                __nv_bfloat162 p0, p1;
                p0.x = __float2bfloat16(o0.x); p0.y = __float2bfloat16(o0.y);
                p1.x = __float2bfloat16(o1.x); p1.y = __float2bfloat16(o1.y);
                *reinterpret_cast<__nv_bfloat162*>(&C[(size_t)row0 * ldC + col]) = p0;
                *reinterpret_cast<__nv_bfloat162*>(&C[(size_t)(row0 + 8) * ldC + col]) = p1;
            } else {
                *reinterpret_cast<float2*>(&C[(size_t)row0 * ldC + col]) = o0;
                *reinterpret_cast<float2*>(&C[(size_t)(row0 + 8) * ldC + col]) = o1;
            }
        }
    }
}

// ---------------- sampling: lane-specialized math + shfl broadcast, bf16 v ----------------
__global__ void __launch_bounds__(256)
sample_kernel(const float* __restrict__ refp, const float* __restrict__ oa,
              float* __restrict__ outp)
{
    const int lane = threadIdx.x & 31;
    const int h    = threadIdx.x >> 5;
    const int bq   = blockIdx.x;
    const int b    = bq / NQ;

    const float* oabase = oa + (size_t)bq * 96;

    float aw = 0.f, ox = 0.f, oy = 0.f;
    if (lane < 4) {
        aw = oabase[64 + h * 4 + lane];
        const float* op = oabase + h * 8 + 2 * lane;
        ox = op[0]; oy = op[1];
    }
    float m = fmaxf(aw, __shfl_xor_sync(0xffffffffu, aw, 1));
    m = fmaxf(m, __shfl_xor_sync(0xffffffffu, m, 2));
    float e = __expf(aw - m);
    float s = e + __shfl_xor_sync(0xffffffffu, e, 1);
    s = s + __shfl_xor_sync(0xffffffffu, s, 2);
    const float wp = e / s;

    const float rx = refp[(size_t)bq * 2 + 0];
    const float ry = refp[(size_t)bq * 2 + 1];

    int   i00 = 0, i01 = 0, i10 = 0, i11 = 0;
    float w00 = 0.f, w01 = 0.f, w10 = 0.f, w11 = 0.f;
    {
        float locx = rx + ox * (1.f / (float)SW);
        float locy = ry + oy * (1.f / (float)SH);
        float gx = 2.f * locx - 1.f;
        float gy = 2.f * locy - 1.f;
        float px = ((gx + 1.f) * (float)SW - 1.f) * 0.5f;
        float py = ((gy + 1.f) * (float)SH - 1.f) * 0.5f;
        float x0f = floorf(px), y0f = floorf(py);
        int   x0 = (int)x0f,    y0 = (int)y0f;
        float fx = px - x0f,    fy = py - y0f;

        const bool xv0 = (x0 >= 0)     && (x0 <= SW - 1);
        const bool xv1 = (x0 + 1 >= 0) && (x0 + 1 <= SW - 1);
        const bool yv0 = (y0 >= 0)     && (y0 <= SH - 1);
        const bool yv1 = (y0 + 1 >= 0) && (y0 + 1 <= SH - 1);

        int xc0 = min(max(x0, 0), SW - 1);
        int xc1 = min(max(x0 + 1, 0), SW - 1);
        int yc0 = min(max(y0, 0), SH - 1);
        int yc1 = min(max(y0 + 1, 0), SH - 1);

        w00 = (xv0 && yv0) ? wp * (1.f - fx) * (1.f - fy) : 0.f;
        w01 = (xv1 && yv0) ? wp * fx * (1.f - fy)         : 0.f;
        w10 = (xv0 && yv1) ? wp * (1.f - fx) * fy         : 0.f;
        w11 = (xv1 && yv1) ? wp * fx * fy                 : 0.f;

        i00 = (yc0 * SW + xc0) * EMBED;
        i01 = (yc0 * SW + xc1) * EMBED;
        i10 = (yc1 * SW + xc0) * EMBED;
        i11 = (yc1 * SW + xc1) * EMBED;
    }

    const __nv_bfloat16* vbase = g_v + (size_t)b * NV * EMBED + h * HEAD_DIM + lane;

    float acc = 0.f;
#pragma unroll
    for (int p = 0; p < POINTS; p++) {
        const int   j00 = __shfl_sync(0xffffffffu, i00, p);
        const int   j01 = __shfl_sync(0xffffffffu, i01, p);
        const int   j10 = __shfl_sync(0xffffffffu, i10, p);
        const int   j11 = __shfl_sync(0xffffffffu, i11, p);
        const float u00 = __shfl_sync(0xffffffffu, w00, p);
        const float u01 = __shfl_sync(0xffffffffu, w01, p);
        const float u10 = __shfl_sync(0xffffffffu, w10, p);
        const float u11 = __shfl_sync(0xffffffffu, w11, p);
        float v00 = __bfloat162float(vbase[j00]);
        float v01 = __bfloat162float(vbase[j01]);
        float v10 = __bfloat162float(vbase[j10]);
        float v11 = __bfloat162float(vbase[j11]);
        acc = fmaf(u00, v00, acc);
        acc = fmaf(u01, v01, acc);
        acc = fmaf(u10, v10, acc);
        acc = fmaf(u11, v11, acc);
    }

    outp[(size_t)bq * EMBED + h * HEAD_DIM + lane] = acc;
}

// ---------------- launch ----------------
extern "C" void kernel_launch(void* const* d_in, const int* in_sizes, int n_in,
                              void* d_out, int out_size)
{
    const float* query   = (const float*)d_in[0];
    const float* value   = (const float*)d_in[1];
    const float* refpts  = (const float*)d_in[2];
    const float* W_value = (const float*)d_in[4];
    const float* b_value = (const float*)d_in[5];
    const float* W_off   = (const float*)d_in[6];
    const float* b_off   = (const float*)d_in[7];
    const float* W_attn  = (const float*)d_in[8];
    const float* b_attn  = (const float*)d_in[9];
    const float* W_out   = (const float*)d_in[10];
    const float* b_out   = (const float*)d_in[11];
    float* out = (float*)d_out;

    __nv_bfloat16 *pv;
    float *poa, *ptmp, *pboa;
    __nv_bfloat16 *wv_h, *wv_l, *wo_h, *wo_l, *woa_h, *woa_l;
    cudaGetSymbolAddress((void**)&pv,    g_v);
    cudaGetSymbolAddress((void**)&poa,   g_oa);
    cudaGetSymbolAddress((void**)&ptmp,  g_tmp);
    cudaGetSymbolAddress((void**)&pboa,  g_boa);
    cudaGetSymbolAddress((void**)&wv_h,  g_Wv_hi);  cudaGetSymbolAddress((void**)&wv_l,  g_Wv_lo);
    cudaGetSymbolAddress((void**)&wo_h,  g_Wo_hi);  cudaGetSymbolAddress((void**)&wo_l,  g_Wo_lo);
    cudaGetSymbolAddress((void**)&woa_h, g_Woa_hi); cudaGetSymbolAddress((void**)&woa_l, g_Woa_lo);

    const int SMEM_128 = (2 * 128 + 2 * 128) * 144; // 73728
    const int SMEM_96  = (2 * 128 + 2 *  96) * 144; // 64512
    cudaFuncSetAttribute((const void*)mma_gemm_kernel<128, false, __nv_bfloat16>,
                         cudaFuncAttributeMaxDynamicSharedMemorySize, SMEM_128);
    cudaFuncSetAttribute((const void*)mma_gemm_kernel<128, true, float>,
                         cudaFuncAttributeMaxDynamicSharedMemorySize, SMEM_128);
    cudaFuncSetAttribute((const void*)mma_gemm_kernel<96, false, float>,
                         cudaFuncAttributeMaxDynamicSharedMemorySize, SMEM_96);

    // weight transpose + bf16 split
    convert_w_kernel<<<(256 * 256 + 255) / 256, 256>>>(W_value, wv_h, wv_l, 256);
    convert_w_kernel<<<(256 * 256 + 255) / 256, 256>>>(W_out,   wo_h, wo_l, 256);
    convert_oa_kernel<<<(96 * 256 + 255) / 256, 256>>>(W_off, b_off, W_attn, b_attn,
                                                       woa_h, woa_l, pboa);

    const int GRID = MROWS / 128; // 625

    // 1) v = value @ W_value + b_value  -> bf16  (N=256 split into 2x128)
    mma_gemm_kernel<128, false, __nv_bfloat16><<<dim3(GRID, 2), 256, SMEM_128>>>(
        value, wv_h, wv_l, b_value, nullptr, pv, 256);
    // 2+3) [off|attn] = query @ [W_off|W_attn] + bias   (N=96)
    mma_gemm_kernel<96, false, float><<<dim3(GRID, 1), 256, SMEM_96>>>(
        query, woa_h, woa_l, pboa, nullptr, poa, 96);
    // 4) softmax + bilinear sample (bf16 gathers)
    sample_kernel<<<BS * NQ, 256>>>(refpts, poa, ptmp);
    // 5) out = tmp @ W_out + b_out + query   (N=256 split into 2x128)
    mma_gemm_kernel<128, true, float><<<dim3(GRID, 2), 256, SMEM_128>>>(
        ptmp, wo_h, wo_l, b_out, query, out, 256);
}

// round 8
// speedup vs baseline: 1.1428x; 1.1428x over previous
#include <cuda_runtime.h>
#include <cuda_bf16.h>
#include <math.h>
#include <stdint.h>

// ---------------- problem constants ----------------
#define BS      2
#define NQ      40000
#define NV      40000
#define EMBED   256
#define HEADS   8
#define POINTS  4
#define HEAD_DIM 32
#define SH      200
#define SW      200
#define MROWS   (BS * NQ)      // 80000

// ---------------- device scratch ----------------
__device__ float g_v   [(size_t)BS * NV * EMBED];        // projected value (fp32)
__device__ float g_oa  [(size_t)BS * NQ * 96];           // fused [off(64) | attn(32)]
__device__ float g_tmp [(size_t)BS * NQ * EMBED];
__device__ float g_boa [96];
// transposed + split weights: [N][K] bf16
__device__ __nv_bfloat16 g_Wv_hi [256 * 256], g_Wv_lo [256 * 256];
__device__ __nv_bfloat16 g_Wo_hi [256 * 256], g_Wo_lo [256 * 256];
__device__ __nv_bfloat16 g_Woa_hi[ 96 * 256], g_Woa_lo[ 96 * 256];

// ---------------- warp mma / ldmatrix helpers ----------------
__device__ __forceinline__ void mma_bf16(float* d, const uint32_t* a, const uint32_t* b) {
    asm volatile(
        "mma.sync.aligned.m16n8k16.row.col.f32.bf16.bf16.f32 "
        "{%0,%1,%2,%3}, {%4,%5,%6,%7}, {%8,%9}, {%0,%1,%2,%3};"
        : "+f"(d[0]), "+f"(d[1]), "+f"(d[2]), "+f"(d[3])
        : "r"(a[0]), "r"(a[1]), "r"(a[2]), "r"(a[3]), "r"(b[0]), "r"(b[1]));
}
__device__ __forceinline__ void ldsm_x4(uint32_t& r0, uint32_t& r1, uint32_t& r2, uint32_t& r3,
                                        uint32_t addr) {
    asm volatile("ldmatrix.sync.aligned.m8n8.x4.shared.b16 {%0,%1,%2,%3}, [%4];"
                 : "=r"(r0), "=r"(r1), "=r"(r2), "=r"(r3) : "r"(addr));
}
__device__ __forceinline__ void ldsm_x2(uint32_t& r0, uint32_t& r1, uint32_t addr) {
    asm volatile("ldmatrix.sync.aligned.m8n8.x2.shared.b16 {%0,%1}, [%2];"
                 : "=r"(r0), "=r"(r1) : "r"(addr));
}

// ---------------- weight transpose + bf16 split ----------------
__global__ void convert_w_kernel(const float* __restrict__ W,
                                 __nv_bfloat16* __restrict__ hi,
                                 __nv_bfloat16* __restrict__ lo, int N)
{
    int idx = blockIdx.x * 256 + threadIdx.x;
    if (idx >= N * 256) return;
    int n = idx >> 8, k = idx & 255;
    float v = W[k * N + n];
    __nv_bfloat16 h = __float2bfloat16(v);
    hi[idx] = h;
    lo[idx] = __float2bfloat16(v - __bfloat162float(h));
}

__global__ void convert_oa_kernel(const float* __restrict__ Woff, const float* __restrict__ boff,
                                  const float* __restrict__ Wattn, const float* __restrict__ battn,
                                  __nv_bfloat16* __restrict__ hi, __nv_bfloat16* __restrict__ lo,
                                  float* __restrict__ bcomb)
{
    int idx = blockIdx.x * 256 + threadIdx.x;
    if (idx >= 96 * 256) return;
    int n = idx >> 8, k = idx & 255;
    float v = (n < 64) ? Woff[k * 64 + n] : Wattn[k * 32 + (n - 64)];
    __nv_bfloat16 h = __float2bfloat16(v);
    hi[idx] = h;
    lo[idx] = __float2bfloat16(v - __bfloat162float(h));
    if (idx < 96) bcomb[idx] = (idx < 64) ? boff[idx] : battn[idx - 64];
}

// ---------------- split-bf16 HMMA GEMM: ldmatrix fragment loads ----------------
template<int BN, bool RES>
__global__ void __launch_bounds__(256, 2)
mma_gemm_kernel(const float* __restrict__ A,
                const __nv_bfloat16* __restrict__ Bt_hi,
                const __nv_bfloat16* __restrict__ Bt_lo,
                const float* __restrict__ bias,
                const float* __restrict__ res,
                float* __restrict__ C, int ldC)
{
    constexpr int K = 256, BK = 64, BM = 128;
    constexpr int WN  = 4;
    constexpr int WTN = BN / WN;
    constexpr int MT  = 4;
    constexpr int NTI = WTN / 8;
    constexpr int NPAIR = NTI / 2;
    constexpr int AST = 144;
    constexpr int A_H = 0;
    constexpr int A_L = BM * AST;
    constexpr int B_H = 2 * BM * AST;
    constexpr int B_L = B_H + BN * AST;

    extern __shared__ char sm[];

    const int tid  = threadIdx.x;
    const int wid  = tid >> 5;
    const int lane = tid & 31;
    const int g    = lane >> 2;
    const int c    = lane & 3;
    const int wm   = wid / WN;
    const int wn   = wid % WN;
    const int wmBase = wm * 64;
    const int wnBase = wn * WTN;
    const int bm   = blockIdx.x;
    const int nOff = blockIdx.y * BN;

    float acc[MT][NTI][4];
#pragma unroll
    for (int i = 0; i < MT; i++)
#pragma unroll
        for (int j = 0; j < NTI; j++)
#pragma unroll
            for (int q = 0; q < 4; q++) acc[i][j][q] = 0.f;

    const int aRow = wmBase + (lane & 15);
    const int aKs  = (lane >> 4) * 16;
    const int bRow = wnBase + ((lane >> 4) << 3) + (lane & 7);
    const int bKs  = ((lane >> 3) & 1) * 16;
    const uint32_t aHiB = (uint32_t)__cvta_generic_to_shared(sm + A_H + aRow * AST + aKs);
    const uint32_t aLoB = aHiB + (uint32_t)(A_L - A_H);
    const uint32_t bHiB = (uint32_t)__cvta_generic_to_shared(sm + B_H + bRow * AST + bKs);
    const uint32_t bLoB = bHiB + (uint32_t)(B_L - B_H);

    for (int it = 0; it < K / BK; it++) {
        const int k0 = it * BK;
#pragma unroll
        for (int f = tid; f < BM * 16; f += 256) {
            const int r = f >> 4, c4 = f & 15;
            float4 a = *reinterpret_cast<const float4*>(
                &A[(size_t)(bm * BM + r) * K + k0 + c4 * 4]);
            __nv_bfloat16 h0 = __float2bfloat16(a.x);
            __nv_bfloat16 h1 = __float2bfloat16(a.y);
            __nv_bfloat16 h2 = __float2bfloat16(a.z);
            __nv_bfloat16 h3 = __float2bfloat16(a.w);
            __nv_bfloat16 l0 = __float2bfloat16(a.x - __bfloat162float(h0));
            __nv_bfloat16 l1 = __float2bfloat16(a.y - __bfloat162float(h1));
            __nv_bfloat16 l2 = __float2bfloat16(a.z - __bfloat162float(h2));
            __nv_bfloat16 l3 = __float2bfloat16(a.w - __bfloat162float(h3));
            uint32_t hA = ((uint32_t)__bfloat16_as_ushort(h1) << 16) | __bfloat16_as_ushort(h0);
            uint32_t hB = ((uint32_t)__bfloat16_as_ushort(h3) << 16) | __bfloat16_as_ushort(h2);
            uint32_t lA = ((uint32_t)__bfloat16_as_ushort(l1) << 16) | __bfloat16_as_ushort(l0);
            uint32_t lB = ((uint32_t)__bfloat16_as_ushort(l3) << 16) | __bfloat16_as_ushort(l2);
            uint2 vh; vh.x = hA; vh.y = hB;
            uint2 vl; vl.x = lA; vl.y = lB;
            *reinterpret_cast<uint2*>(sm + A_H + r * AST + c4 * 8) = vh;
            *reinterpret_cast<uint2*>(sm + A_L + r * AST + c4 * 8) = vl;
        }
#pragma unroll
        for (int f = tid; f < BN * 8; f += 256) {
            const int n = f >> 3, cu = f & 7;
            uint4 hi = *reinterpret_cast<const uint4*>(&Bt_hi[(nOff + n) * K + k0 + cu * 8]);
            uint4 lo = *reinterpret_cast<const uint4*>(&Bt_lo[(nOff + n) * K + k0 + cu * 8]);
            *reinterpret_cast<uint4*>(sm + B_H + n * AST + cu * 16) = hi;
            *reinterpret_cast<uint4*>(sm + B_L + n * AST + cu * 16) = lo;
        }
        __syncthreads();

#pragma unroll
        for (int ks = 0; ks < BK / 16; ks++) {
            const uint32_t kb = ks * 32;
            uint32_t af[MT][4], bh[NTI][2], bl[NTI][2];
#pragma unroll
            for (int p = 0; p < NPAIR; p++)
                ldsm_x4(bh[2*p][0], bh[2*p][1], bh[2*p+1][0], bh[2*p+1][1],
                        bHiB + (uint32_t)(p * 16 * AST) + kb);
            if (NTI & 1)
                ldsm_x2(bh[NTI-1][0], bh[NTI-1][1],
                        bHiB + (uint32_t)((NTI-1) * 8 * AST) + kb);
#pragma unroll
            for (int mi = 0; mi < MT; mi++)
                ldsm_x4(af[mi][0], af[mi][1], af[mi][2], af[mi][3],
                        aHiB + (uint32_t)(mi * 16 * AST) + kb);
#pragma unroll
            for (int mi = 0; mi < MT; mi++)
#pragma unroll
                for (int ni = 0; ni < NTI; ni++)
                    mma_bf16(acc[mi][ni], af[mi], bh[ni]);
#pragma unroll
            for (int p = 0; p < NPAIR; p++)
                ldsm_x4(bl[2*p][0], bl[2*p][1], bl[2*p+1][0], bl[2*p+1][1],
                        bLoB + (uint32_t)(p * 16 * AST) + kb);
            if (NTI & 1)
                ldsm_x2(bl[NTI-1][0], bl[NTI-1][1],
                        bLoB + (uint32_t)((NTI-1) * 8 * AST) + kb);
#pragma unroll
            for (int mi = 0; mi < MT; mi++)
#pragma unroll
                for (int ni = 0; ni < NTI; ni++)
                    mma_bf16(acc[mi][ni], af[mi], bl[ni]);
#pragma unroll
            for (int mi = 0; mi < MT; mi++)
                ldsm_x4(af[mi][0], af[mi][1], af[mi][2], af[mi][3],
                        aLoB + (uint32_t)(mi * 16 * AST) + kb);
#pragma unroll
            for (int mi = 0; mi < MT; mi++)
#pragma unroll
                for (int ni = 0; ni < NTI; ni++)
                    mma_bf16(acc[mi][ni], af[mi], bh[ni]);
        }
        __syncthreads();
    }

    // ---- epilogue ----
#pragma unroll
    for (int mi = 0; mi < MT; mi++) {
        const int row0 = bm * BM + wmBase + mi * 16 + g;
#pragma unroll
        for (int ni = 0; ni < NTI; ni++) {
            const int col = nOff + wnBase + ni * 8 + c * 2;
            float2 bb = *reinterpret_cast<const float2*>(&bias[col]);
            float2 o0, o1;
            o0.x = acc[mi][ni][0] + bb.x;
            o0.y = acc[mi][ni][1] + bb.y;
            o1.x = acc[mi][ni][2] + bb.x;
            o1.y = acc[mi][ni][3] + bb.y;
            if constexpr (RES) {
                float2 r0 = *reinterpret_cast<const float2*>(&res[(size_t)row0 * ldC + col]);
                float2 r1 = *reinterpret_cast<const float2*>(&res[(size_t)(row0 + 8) * ldC + col]);
                o0.x += r0.x; o0.y += r0.y;
                o1.x += r1.x; o1.y += r1.y;
            }
            *reinterpret_cast<float2*>(&C[(size_t)row0 * ldC + col]) = o0;
            *reinterpret_cast<float2*>(&C[(size_t)(row0 + 8) * ldC + col]) = o1;
        }
    }
}

// ---------------- sampling v3: 2 heads per warp, float2 channel pairs ----------------
// Block = 256 threads = 8 warps, handles 2 queries (warps 0-3 -> q0, 4-7 -> q1).
// Warp w: heads h0=(w&3)*2 (lanes 0-15) and h1=h0+1 (lanes 16-31); lane owns
// channel pair 2*(lane&15). Geometry for 8 (head,point) pairs on lanes 0-7,
// broadcast via variable-source shfl serving both halves at once.
__global__ void __launch_bounds__(256)
sample_kernel(const float* __restrict__ refp, const float* __restrict__ oa,
              float* __restrict__ outp)
{
    const int lane  = threadIdx.x & 31;
    const int wid   = threadIdx.x >> 5;
    const int bq    = blockIdx.x * 2 + (wid >> 2);
    const int b     = bq / NQ;
    const int hPair = (wid & 3) * 2;
    const int half  = lane >> 4;            // 0 -> h0, 1 -> h1
    const int h     = hPair + half;
    const int ch    = lane & 15;            // channel-pair index

    const float* oabase = oa + (size_t)bq * 96;

    // lanes 0..7: geometry for (head hPair + (lane>>2), point lane&3)
    float aw = 0.f, ox = 0.f, oy = 0.f;
    {
        const int hg = hPair + ((lane >> 2) & 1);
        const int p  = lane & 3;
        if (lane < 8) {
            aw = oabase[64 + hg * 4 + p];
            ox = oabase[hg * 8 + 2 * p];
            oy = oabase[hg * 8 + 2 * p + 1];
        }
    }
    // softmax within each quad (lanes 0-3 and 4-7 reduce independently under xor)
    float m = fmaxf(aw, __shfl_xor_sync(0xffffffffu, aw, 1));
    m = fmaxf(m, __shfl_xor_sync(0xffffffffu, m, 2));
    float e = __expf(aw - m);
    float s = e + __shfl_xor_sync(0xffffffffu, e, 1);
    s = s + __shfl_xor_sync(0xffffffffu, s, 2);
    const float wp = e / s;                 // valid on lanes 0..7

    const float rx = refp[(size_t)bq * 2 + 0];
    const float ry = refp[(size_t)bq * 2 + 1];

    int   i00 = 0, i01 = 0, i10 = 0, i11 = 0;   // float2-unit offsets (idx * 128)
    float w00 = 0.f, w01 = 0.f, w10 = 0.f, w11 = 0.f;
    {
        float locx = rx + ox * (1.f / (float)SW);
        float locy = ry + oy * (1.f / (float)SH);
        float gx = 2.f * locx - 1.f;
        float gy = 2.f * locy - 1.f;
        float px = ((gx + 1.f) * (float)SW - 1.f) * 0.5f;
        float py = ((gy + 1.f) * (float)SH - 1.f) * 0.5f;
        float x0f = floorf(px), y0f = floorf(py);
        int   x0 = (int)x0f,    y0 = (int)y0f;
        float fx = px - x0f,    fy = py - y0f;

        const bool xv0 = (x0 >= 0)     && (x0 <= SW - 1);
        const bool xv1 = (x0 + 1 >= 0) && (x0 + 1 <= SW - 1);
        const bool yv0 = (y0 >= 0)     && (y0 <= SH - 1);
        const bool yv1 = (y0 + 1 >= 0) && (y0 + 1 <= SH - 1);

        int xc0 = min(max(x0, 0), SW - 1);
        int xc1 = min(max(x0 + 1, 0), SW - 1);
        int yc0 = min(max(y0, 0), SH - 1);
        int yc1 = min(max(y0 + 1, 0), SH - 1);

        w00 = (xv0 && yv0) ? wp * (1.f - fx) * (1.f - fy) : 0.f;
        w01 = (xv1 && yv0) ? wp * fx * (1.f - fy)         : 0.f;
        w10 = (xv0 && yv1) ? wp * (1.f - fx) * fy         : 0.f;
        w11 = (xv1 && yv1) ? wp * fx * fy                 : 0.f;

        i00 = (yc0 * SW + xc0) * (EMBED / 2);
        i01 = (yc0 * SW + xc1) * (EMBED / 2);
        i10 = (yc1 * SW + xc0) * (EMBED / 2);
        i11 = (yc1 * SW + xc1) * (EMBED / 2);
    }

    const float2* vbase = reinterpret_cast<const float2*>(
        g_v + (size_t)b * NV * EMBED + h * HEAD_DIM) + ch;

    float2 acc; acc.x = 0.f; acc.y = 0.f;
#pragma unroll
    for (int p = 0; p < POINTS; p++) {
        const int src = half * 4 + p;       // lane holding this half's point-p geometry
        const int   j00 = __shfl_sync(0xffffffffu, i00, src);
        const int   j01 = __shfl_sync(0xffffffffu, i01, src);
        const int   j10 = __shfl_sync(0xffffffffu, i10, src);
        const int   j11 = __shfl_sync(0xffffffffu, i11, src);
        const float u00 = __shfl_sync(0xffffffffu, w00, src);
        const float u01 = __shfl_sync(0xffffffffu, w01, src);
        const float u10 = __shfl_sync(0xffffffffu, w10, src);
        const float u11 = __shfl_sync(0xffffffffu, w11, src);
        float2 v00 = vbase[j00];
        float2 v01 = vbase[j01];
        float2 v10 = vbase[j10];
        float2 v11 = vbase[j11];
        acc.x = fmaf(u00, v00.x, acc.x); acc.y = fmaf(u00, v00.y, acc.y);
        acc.x = fmaf(u01, v01.x, acc.x); acc.y = fmaf(u01, v01.y, acc.y);
        acc.x = fmaf(u10, v10.x, acc.x); acc.y = fmaf(u10, v10.y, acc.y);
        acc.x = fmaf(u11, v11.x, acc.x); acc.y = fmaf(u11, v11.y, acc.y);
    }

    *reinterpret_cast<float2*>(&outp[(size_t)bq * EMBED + h * HEAD_DIM + ch * 2]) = acc;
}

// ---------------- launch ----------------
extern "C" void kernel_launch(void* const* d_in, const int* in_sizes, int n_in,
                              void* d_out, int out_size)
{
    const float* query   = (const float*)d_in[0];
    const float* value   = (const float*)d_in[1];
    const float* refpts  = (const float*)d_in[2];
    const float* W_value = (const float*)d_in[4];
    const float* b_value = (const float*)d_in[5];
    const float* W_off   = (const float*)d_in[6];
    const float* b_off   = (const float*)d_in[7];
    const float* W_attn  = (const float*)d_in[8];
    const float* b_attn  = (const float*)d_in[9];
    const float* W_out   = (const float*)d_in[10];
    const float* b_out   = (const float*)d_in[11];
    float* out = (float*)d_out;

    float *pv, *poa, *ptmp, *pboa;
    __nv_bfloat16 *wv_h, *wv_l, *wo_h, *wo_l, *woa_h, *woa_l;
    cudaGetSymbolAddress((void**)&pv,    g_v);
    cudaGetSymbolAddress((void**)&poa,   g_oa);
    cudaGetSymbolAddress((void**)&ptmp,  g_tmp);
    cudaGetSymbolAddress((void**)&pboa,  g_boa);
    cudaGetSymbolAddress((void**)&wv_h,  g_Wv_hi);  cudaGetSymbolAddress((void**)&wv_l,  g_Wv_lo);
    cudaGetSymbolAddress((void**)&wo_h,  g_Wo_hi);  cudaGetSymbolAddress((void**)&wo_l,  g_Wo_lo);
    cudaGetSymbolAddress((void**)&woa_h, g_Woa_hi); cudaGetSymbolAddress((void**)&woa_l, g_Woa_lo);

    const int SMEM_128 = (2 * 128 + 2 * 128) * 144; // 73728
    const int SMEM_96  = (2 * 128 + 2 *  96) * 144; // 64512
    cudaFuncSetAttribute(mma_gemm_kernel<128, false>, cudaFuncAttributeMaxDynamicSharedMemorySize, SMEM_128);
    cudaFuncSetAttribute(mma_gemm_kernel<128, true >, cudaFuncAttributeMaxDynamicSharedMemorySize, SMEM_128);
    cudaFuncSetAttribute(mma_gemm_kernel< 96, false>, cudaFuncAttributeMaxDynamicSharedMemorySize, SMEM_96);

    // weight transpose + bf16 split
    convert_w_kernel<<<(256 * 256 + 255) / 256, 256>>>(W_value, wv_h, wv_l, 256);
    convert_w_kernel<<<(256 * 256 + 255) / 256, 256>>>(W_out,   wo_h, wo_l, 256);
    convert_oa_kernel<<<(96 * 256 + 255) / 256, 256>>>(W_off, b_off, W_attn, b_attn,
                                                       woa_h, woa_l, pboa);

    const int GRID = MROWS / 128; // 625

    // 1) v = value @ W_value + b_value       (N=256 split into 2x128)
    mma_gemm_kernel<128, false><<<dim3(GRID, 2), 256, SMEM_128>>>(
        value, wv_h, wv_l, b_value, nullptr, pv, 256);
    // 2+3) [off|attn] = query @ [W_off|W_attn] + bias   (N=96)
    mma_gemm_kernel<96, false><<<dim3(GRID, 1), 256, SMEM_96>>>(
        query, woa_h, woa_l, pboa, nullptr, poa, 96);
    // 4) softmax + bilinear sample (2 heads/warp, float2 channels)
    sample_kernel<<<MROWS / 2, 256>>>(refpts, poa, ptmp);
    // 5) out = tmp @ W_out + b_out + query   (N=256 split into 2x128)
    mma_gemm_kernel<128, true><<<dim3(GRID, 2), 256, SMEM_128>>>(
        ptmp, wo_h, wo_l, b_out, query, out, 256);
}